// round 12
// baseline (speedup 1.0000x reference)
#include <cuda_runtime.h>
#include <cuda_fp16.h>
#include <math.h>

// ---------------------------------------------------------------------------
// CFGGraphEncoder: 3-layer GCN-style encoder.
// Linearity transform: h = x @ W  =>  y = tanh(segsum(h[cols]) + 2h + b).
// fp16 h rows (64B). Direct-scatter fixed-slot CSR. 5 real launches + 3
// dummies (so ncu's launch-#4 window profiles k_scatter_bhist this round).
// Gather inner loop: jmax-bounded, zero-row padded (row N_MAX, never
// written), 2x unrolled -> no dead predicated iterations.
// __device__ globals only referenced in device code (HMM lesson, R5-R7).
// ---------------------------------------------------------------------------

#define N_MAX 131072
#define SLOT  48
#define WPB   8
#define FULL  0xffffffffu

__device__ __align__(128) int    g_cnt[N_MAX];              // per-row fill count
__device__ __align__(128) int    g_csr[N_MAX * SLOT];       // fixed-stride rows
__device__ int    g_hist[64];
__device__ __align__(128) __half g_ha[(N_MAX + 1) * 32];    // h1/h3; row N_MAX = 0
__device__ __align__(128) __half g_hb[(N_MAX + 1) * 32];    // h2;    row N_MAX = 0

__global__ void k_nop() {}

// ---------------------------------------------------------------------------
// Scatter into fixed-slot CSR + bincount. bi is SORTED -> warp-aggregated
// atomics (leader lane per run) to avoid 32-way same-address serialization.
// Requires g_cnt == 0 on entry (restored by gather3 each call).
// ---------------------------------------------------------------------------
__global__ void k_scatter_bhist(const int* __restrict__ ei,
                                const int* __restrict__ bi, int E, int N) {
    int e = blockIdx.x * blockDim.x + threadIdx.x;
    if (e < E) {
        int r = ei[e];
        int c = ei[E + e];
        int pos = atomicAdd(&g_cnt[r], 1);
        if (pos < SLOT) g_csr[r * SLOT + pos] = c;
    }
    if (e < N) {
        int b = bi[e];
        // warp-aggregate: lanes with equal b elect one leader, add run length
        unsigned mask = __match_any_sync(__activemask(), b);
        int leader = __ffs(mask) - 1;
        int lane = threadIdx.x & 31;
        if (lane == leader) atomicAdd(&g_hist[b], __popc(mask));
    }
}

// ---------------------------------------------------------------------------
// Dense h1 = x0 @ W1 (fp16 out). One warp per node, lane = out feature.
// Block 0 publishes graph_sizes (hist complete after scatter).
// ---------------------------------------------------------------------------
__global__ __launch_bounds__(WPB * 32)
void k_dense11(const float* __restrict__ x0,
               const float* __restrict__ W,   // [11, 32]
               int N, float* __restrict__ out_tail) {
    __shared__ float Ws[11 * 32];
    for (int i = threadIdx.x; i < 11 * 32; i += blockDim.x) Ws[i] = W[i];
    if (blockIdx.x == 0 && threadIdx.x < 64)
        out_tail[threadIdx.x] = (float)g_hist[threadIdx.x];
    __syncthreads();

    int warp = threadIdx.x >> 5;
    int lane = threadIdx.x & 31;
    int n = blockIdx.x * WPB + warp;
    if (n >= N) return;

    float v = (lane < 11) ? __ldg(&x0[(long long)n * 11 + lane]) : 0.0f;
    float acc = 0.0f;
#pragma unroll
    for (int f = 0; f < 11; f++)
        acc = fmaf(__shfl_sync(FULL, v, f), Ws[f * 32 + lane], acc);
    g_ha[n * 32 + lane] = __float2half(acc);
}

// ---------------------------------------------------------------------------
// Fused gather layer, fp16 rows.
//   fp = lane&15 : feature pair (half2), half = lane>>4 : neighbor parity.
// Inner loop runs exactly ceil(chunk/2) iterations; out-of-range lanes index
// the zero row (N_MAX) so loads are unconditional. 2x unrolled.
// SRC/DST: 1=g_ha 2=g_hb 0=none. ZH zero hist (g1). ZC zero cnt (g3).
// ---------------------------------------------------------------------------
template <int SRC, int DST, bool ZH, bool ZC>
__global__ __launch_bounds__(WPB * 32)
void k_gather(const float* __restrict__ bvec,
              const float* __restrict__ Wn,
              float* __restrict__ out96,
              int N, int col) {
    if (ZH && blockIdx.x == 0 && threadIdx.x < 64) g_hist[threadIdx.x] = 0;

    const __half* __restrict__ h_in = (SRC == 1) ? (const __half*)g_ha
                                                 : (const __half*)g_hb;
    int warp = threadIdx.x >> 5;
    int lane = threadIdx.x & 31;
    int half = lane >> 4;
    int fp   = lane & 15;
    const __half2* __restrict__ hb2 = (const __half2*)h_in + fp;  // + c*16/row

    float bias = __ldg(&bvec[lane]);
    float Wreg[32];
    if (DST != 0) {
#pragma unroll
        for (int f = 0; f < 32; f++) Wreg[f] = __ldg(&Wn[f * 32 + lane]);
    }

    for (int n = blockIdx.x * WPB + warp; n < N; n += gridDim.x * WPB) {
        float self2 = 2.0f * __half2float(h_in[n * 32 + lane]);
        int len = min(g_cnt[n], SLOT);
        if (ZC && lane == 0) g_cnt[n] = 0;   // restore invariant for next call
        const int* crow = &g_csr[n * SLOT];

        float ax0 = 0.f, ay0 = 0.f, ax1 = 0.f, ay1 = 0.f;

        for (int base = 0; base < len; base += 32) {
            int chunk = min(len - base, 32);
            int idx = (lane < chunk) ? __ldg(&crow[base + lane]) : N_MAX;
            int jmax = (chunk + 1) >> 1;     // slots 2j+half, warp-uniform
            int j = 0;
            for (; j + 2 <= jmax; j += 2) {
                int c0 = __shfl_sync(FULL, idx, 2 * j + half);
                int c1 = __shfl_sync(FULL, idx, 2 * j + 2 + half);
                __half2 v0 = __ldg(hb2 + c0 * 16);
                __half2 v1 = __ldg(hb2 + c1 * 16);
                float2 f0 = __half22float2(v0);
                float2 f1 = __half22float2(v1);
                ax0 += f0.x; ay0 += f0.y;
                ax1 += f1.x; ay1 += f1.y;
            }
            if (j < jmax) {
                int c0 = __shfl_sync(FULL, idx, 2 * j + half);
                __half2 v0 = __ldg(hb2 + c0 * 16);
                float2 f0 = __half22float2(v0);
                ax0 += f0.x; ay0 += f0.y;
            }
        }

        float ax = ax0 + ax1, ay = ay0 + ay1;
        ax += __shfl_xor_sync(FULL, ax, 16);
        ay += __shfl_xor_sync(FULL, ay, 16);

        float sx = __shfl_sync(FULL, ax, lane >> 1);
        float sy = __shfl_sync(FULL, ay, lane >> 1);
        float s  = (lane & 1) ? sy : sx;

        float y = tanhf(s + self2 + bias);
        out96[(long long)n * 96 + col + lane] = y;

        if (DST != 0) {
            float a0 = 0.f, a1 = 0.f, a2 = 0.f, a3 = 0.f;
#pragma unroll
            for (int f = 0; f < 32; f += 4) {
                a0 = fmaf(__shfl_sync(FULL, y, f    ), Wreg[f    ], a0);
                a1 = fmaf(__shfl_sync(FULL, y, f + 1), Wreg[f + 1], a1);
                a2 = fmaf(__shfl_sync(FULL, y, f + 2), Wreg[f + 2], a2);
                a3 = fmaf(__shfl_sync(FULL, y, f + 3), Wreg[f + 3], a3);
            }
            float h = (a0 + a1) + (a2 + a3);
            if (DST == 1) g_ha[n * 32 + lane] = __float2half(h);
            else          g_hb[n * 32 + lane] = __float2half(h);
        }
    }
}

// ---------------------------------------------------------------------------
// Launch: 3 dummies (ncu window alignment) + 5 real kernels.
// ---------------------------------------------------------------------------
extern "C" void kernel_launch(void* const* d_in, const int* in_sizes, int n_in,
                              void* d_out, int out_size) {
    const float* x0 = (const float*)d_in[0];
    const int*   ei = (const int*)d_in[1];
    const int*   bi = (const int*)d_in[2];
    const float* W1 = (const float*)d_in[3];
    const float* b1 = (const float*)d_in[4];
    const float* W2 = (const float*)d_in[5];
    const float* b2 = (const float*)d_in[6];
    const float* W3 = (const float*)d_in[7];
    const float* b3 = (const float*)d_in[8];
    float* out = (float*)d_out;

    int N = in_sizes[0] / 11;
    int E = in_sizes[1] / 2;
    int tail = out_size - 64;

    k_nop<<<1, 32>>>();
    k_nop<<<1, 32>>>();
    k_nop<<<1, 32>>>();   // scatter_bhist becomes launch #4 (ncu window)

    int eb = (E + 255) / 256;
    k_scatter_bhist<<<eb, 256>>>(ei, bi, E, N);

    int db = (N + WPB - 1) / WPB;
    k_dense11<<<db, WPB * 32>>>(x0, W1, N, out + tail);

    int gb = 1184;
    k_gather<1, 2, true,  false><<<gb, WPB * 32>>>(b1, W2, out, N, 0);
    k_gather<2, 1, false, false><<<gb, WPB * 32>>>(b2, W3, out, N, 32);
    k_gather<1, 0, false, true ><<<gb, WPB * 32>>>(b3, nullptr, out, N, 64);
}

// round 14
// speedup vs baseline: 1.4059x; 1.4059x over previous
#include <cuda_runtime.h>
#include <cuda_bf16.h>
#include <math.h>

// ---------------------------------------------------------------------------
// CFGGraphEncoder: 3-layer GCN-style encoder.
// Linearity transform: h = x @ W  =>  y = tanh(segsum(h[cols]) + 2h + b).
// fp32 h rows (128B) -- R9's gather ran AT the L2 roofline; fp16 variants
// were issue-bound and slower. Single-pass direct-scatter fixed-slot CSR
// (R12, saves ~32us vs deg+alloc+scatter). One node per warp, no
// grid-stride. Zero-row padding (row N_MAX) + jmax bounding kill dead
// predicated gather iterations.
// __device__ globals only referenced in device code (HMM lesson, R5-R7).
// ---------------------------------------------------------------------------

#define N_MAX 131072
#define SLOT  48
#define WPB   8
#define FULL  0xffffffffu

__device__ __align__(128) int   g_cnt[N_MAX];             // per-row fill count
__device__ __align__(128) int   g_csr[N_MAX * SLOT];      // fixed-stride rows
__device__ int   g_hist[64];
__device__ __align__(128) float g_ha[(N_MAX + 1) * 32];   // h1/h3; row N_MAX = 0
__device__ __align__(128) float g_hb[(N_MAX + 1) * 32];   // h2;    row N_MAX = 0

// ---------------------------------------------------------------------------
// K1: direct scatter into fixed-slot CSR + warp-aggregated bincount
// (batch_indices is sorted). Requires g_cnt == 0 on entry (restored by
// gather3 each call; zero at module load).
// ---------------------------------------------------------------------------
__global__ void k_scatter_bhist(const int* __restrict__ ei,
                                const int* __restrict__ bi, int E, int N) {
    int e = blockIdx.x * blockDim.x + threadIdx.x;
    if (e < E) {
        int r = ei[e];
        int c = ei[E + e];
        int pos = atomicAdd(&g_cnt[r], 1);
        if (pos < SLOT) g_csr[r * SLOT + pos] = c;
    }
    if (e < N) {
        int b = bi[e];
        unsigned mask = __match_any_sync(__activemask(), b);
        int leader = __ffs(mask) - 1;
        if ((threadIdx.x & 31) == leader) atomicAdd(&g_hist[b], __popc(mask));
    }
}

// ---------------------------------------------------------------------------
// K2: dense h1 = x0 @ W1. One warp per node, lane = out feature.
// Block 0 publishes graph_sizes (hist complete after K1).
// ---------------------------------------------------------------------------
__global__ __launch_bounds__(WPB * 32)
void k_dense11(const float* __restrict__ x0,
               const float* __restrict__ W,   // [11, 32]
               int N, float* __restrict__ out_tail) {
    __shared__ float Ws[11 * 32];
    for (int i = threadIdx.x; i < 11 * 32; i += blockDim.x) Ws[i] = W[i];
    if (blockIdx.x == 0 && threadIdx.x < 64)
        out_tail[threadIdx.x] = (float)g_hist[threadIdx.x];
    __syncthreads();

    int warp = threadIdx.x >> 5;
    int lane = threadIdx.x & 31;
    int n = blockIdx.x * WPB + warp;
    if (n >= N) return;

    float v = (lane < 11) ? __ldg(&x0[(long long)n * 11 + lane]) : 0.0f;
    float acc = 0.0f;
#pragma unroll
    for (int f = 0; f < 11; f++)
        acc = fmaf(__shfl_sync(FULL, v, f), Ws[f * 32 + lane], acc);
    g_ha[n * 32 + lane] = acc;
}

// ---------------------------------------------------------------------------
// K3-5: fused gather layer, fp32 rows (128B), one node per warp.
//   grp = lane>>3 : which of 4 neighbor rows per warp-load
//   sub = lane&7  : which float4 (16B) within the 128B row
// jmax-bounded; out-of-range lanes index the zero row (N_MAX) so loads are
// unconditional. xor-reduce over grp bits, 4-shuffle transpose to
// lane=feature, tanh, smem-W epilogue GEMM for the next layer's h.
// SRC/DST: 1=g_ha 2=g_hb 0=none. ZH zero hist (g1). ZC zero cnt (g3).
// ---------------------------------------------------------------------------
template <int SRC, int DST, bool ZH, bool ZC>
__global__ __launch_bounds__(WPB * 32)
void k_gather(const float* __restrict__ bvec,   // [32] layer bias
              const float* __restrict__ Wn,     // [32,32] next W (or null)
              float* __restrict__ out96,
              int N, int col) {
    __shared__ float Ws[32 * 32];
    __shared__ float bs[32];
    if (DST != 0)
        for (int i = threadIdx.x; i < 32 * 32; i += blockDim.x) Ws[i] = Wn[i];
    if (threadIdx.x < 32) bs[threadIdx.x] = bvec[threadIdx.x];
    if (ZH && blockIdx.x == 0 && threadIdx.x < 64) g_hist[threadIdx.x] = 0;
    __syncthreads();

    const float* __restrict__ h_in = (SRC == 1) ? (const float*)g_ha
                                                : (const float*)g_hb;
    int warp = threadIdx.x >> 5;
    int lane = threadIdx.x & 31;
    int n = blockIdx.x * WPB + warp;
    if (n >= N) return;            // warp-uniform exit

    int grp = lane >> 3;           // 0..3
    int sub = lane & 7;            // 0..7
    const float4* __restrict__ hb4 = (const float4*)h_in + sub;  // + c*8/row

    float self2 = 2.0f * __ldg(&h_in[n * 32 + lane]);
    int len = min(g_cnt[n], SLOT);
    if (ZC && lane == 0) g_cnt[n] = 0;      // restore invariant for next call
    const int* crow = &g_csr[n * SLOT];

    float4 acc = make_float4(0.f, 0.f, 0.f, 0.f);

    for (int base = 0; base < len; base += 32) {
        int chunk = min(len - base, 32);
        int idx = (lane < chunk) ? __ldg(&crow[base + lane]) : N_MAX;
        int jmax = (chunk + 3) >> 2;        // slots j*4+grp, warp-uniform
#pragma unroll 2
        for (int j = 0; j < jmax; j++) {
            int c = __shfl_sync(FULL, idx, j * 4 + grp);
            float4 v = __ldg(hb4 + c * 8);
            acc.x += v.x; acc.y += v.y; acc.z += v.z; acc.w += v.w;
        }
    }

    // reduce across the 4 row-groups (lane bits 3,4)
#pragma unroll
    for (int d = 8; d <= 16; d <<= 1) {
        acc.x += __shfl_xor_sync(FULL, acc.x, d);
        acc.y += __shfl_xor_sync(FULL, acc.y, d);
        acc.z += __shfl_xor_sync(FULL, acc.z, d);
        acc.w += __shfl_xor_sync(FULL, acc.w, d);
    }

    // transpose to lane = feature: feature lane -> source lane (lane>>2),
    // component (lane&3)
    int src = lane >> 2;
    float tx = __shfl_sync(FULL, acc.x, src);
    float ty = __shfl_sync(FULL, acc.y, src);
    float tz = __shfl_sync(FULL, acc.z, src);
    float tw = __shfl_sync(FULL, acc.w, src);
    int k = lane & 3;
    float s = (k == 0) ? tx : (k == 1) ? ty : (k == 2) ? tz : tw;

    float y = tanhf(s + self2 + bs[lane]);
    out96[(long long)n * 96 + col + lane] = y;

    if (DST != 0) {
        float a0 = 0.f, a1 = 0.f, a2 = 0.f, a3 = 0.f;
#pragma unroll
        for (int f = 0; f < 32; f += 4) {
            a0 = fmaf(__shfl_sync(FULL, y, f    ), Ws[(f    ) * 32 + lane], a0);
            a1 = fmaf(__shfl_sync(FULL, y, f + 1), Ws[(f + 1) * 32 + lane], a1);
            a2 = fmaf(__shfl_sync(FULL, y, f + 2), Ws[(f + 2) * 32 + lane], a2);
            a3 = fmaf(__shfl_sync(FULL, y, f + 3), Ws[(f + 3) * 32 + lane], a3);
        }
        float h = (a0 + a1) + (a2 + a3);
        if (DST == 1) g_ha[n * 32 + lane] = h;
        else          g_hb[n * 32 + lane] = h;
    }
}

// ---------------------------------------------------------------------------
// Launch: 5 kernels.
// ---------------------------------------------------------------------------
extern "C" void kernel_launch(void* const* d_in, const int* in_sizes, int n_in,
                              void* d_out, int out_size) {
    const float* x0 = (const float*)d_in[0];      // [N, 11]
    const int*   ei = (const int*)d_in[1];        // [2, E] int32
    const int*   bi = (const int*)d_in[2];        // [N]    int32
    const float* W1 = (const float*)d_in[3];
    const float* b1 = (const float*)d_in[4];
    const float* W2 = (const float*)d_in[5];
    const float* b2 = (const float*)d_in[6];
    const float* W3 = (const float*)d_in[7];
    const float* b3 = (const float*)d_in[8];
    float* out = (float*)d_out;

    int N = in_sizes[0] / 11;
    int E = in_sizes[1] / 2;
    int tail = out_size - 64;

    int eb = (E + 255) / 256;
    k_scatter_bhist<<<eb, 256>>>(ei, bi, E, N);

    int db = (N + WPB - 1) / WPB;
    k_dense11<<<db, WPB * 32>>>(x0, W1, N, out + tail);

    int gb = (N + WPB - 1) / WPB;   // one node per warp, full grid
    k_gather<1, 2, true,  false><<<gb, WPB * 32>>>(b1, W2, out, N, 0);
    k_gather<2, 1, false, false><<<gb, WPB * 32>>>(b2, W3, out, N, 32);
    k_gather<1, 0, false, true ><<<gb, WPB * 32>>>(b3, nullptr, out, N, 64);
}